// round 9
// baseline (speedup 1.0000x reference)
#include <cuda_runtime.h>
#include <cuda_fp16.h>
#include <math_constants.h>
#include <cstdint>

// ---------------- problem constants ----------------
#define NTOK 32768      // 32*32*32 tokens
#define D    256        // embedding dim
#define K    1024       // codebook size
#define HW   1024       // H*W
#define TM   128        // tokens per CTA tile
#define TN   128        // codes per CTA tile
#define KCH  64         // dims per pipeline stage
#define NITER 4         // 4 chunks of 64 dims (hh only)
#define NSTG 3          // cp.async stages
#define STG_BYTES 32768 // A 16KB + B 16KB per stage
#define CAND_CAP 32
#define ESCL      1024.0f          // 2^10 exact
#define ESCL_INV  9.765625e-4f     // 2^-10 exact
// |d_hh - d_exact| <= 4*2^-11*||x||*||e||max + slack
#define T_COEF  1.98e-3f
#define T_SLACK 2.0e-4f

// ---------------- device scratch (no allocations allowed) ----------------
__device__ __align__(256) __half g_Xh[NTOK * D];
__device__ __align__(256) __half g_Eh[K * D];      // fl16(e * 2^10)
__device__ float  g_normX[NTOK];
__device__ float  g_normE[K];
__device__ float  g_maxEblk[8];
__device__ float  g_maxE;
__device__ int    g_cnt[NTOK];
__device__ unsigned long long g_cand[NTOK * CAND_CAP];
__device__ int    g_idx[NTOK];
__device__ double g_partial[1024];

__device__ __forceinline__ uint32_t smem_u32(const void* p) {
    uint32_t a;
    asm("{ .reg .u64 t; cvta.to.shared.u64 t, %1; cvt.u32.u64 %0, t; }" : "=r"(a) : "l"(p));
    return a;
}
#define CP_ASYNC16(saddr, gptr) \
    asm volatile("cp.async.cg.shared.global [%0], [%1], 16;" :: "r"(saddr), "l"(gptr))
#define CP_COMMIT() asm volatile("cp.async.commit_group;" ::: "memory")
#define CP_WAIT1()  asm volatile("cp.async.wait_group 1;" ::: "memory")
#define LDSM_X4(r0, r1, r2, r3, a) \
    asm volatile("ldmatrix.sync.aligned.m8n8.x4.shared.b16 {%0,%1,%2,%3}, [%4];" \
        : "=r"(r0), "=r"(r1), "=r"(r2), "=r"(r3) : "r"(a))
#define MMA_F16(d, a, b0v, b1v) \
    asm volatile("mma.sync.aligned.m16n8k16.row.col.f32.f16.f16.f32 " \
        "{%0,%1,%2,%3}, {%4,%5,%6,%7}, {%8,%9}, {%0,%1,%2,%3};" \
        : "+f"((d)[0]), "+f"((d)[1]), "+f"((d)[2]), "+f"((d)[3]) \
        : "r"((a)[0]), "r"((a)[1]), "r"((a)[2]), "r"((a)[3]), "r"(b0v), "r"(b1v))

__device__ __forceinline__ uint32_t swaddr(int row, int u) {
    return (uint32_t)(row * 128 + ((u ^ (row & 7)) << 4));
}

// ---------------------------------------------------------------------------
// K0: codebook fp16 (pre-scaled by 2^10) + squared norms + per-block max norm
// ---------------------------------------------------------------------------
__global__ void k_prep_e(const float* __restrict__ E) {
    __shared__ float red[128];
    int k = blockIdx.x * blockDim.x + threadIdx.x;
    const float* e = E + (size_t)k * D;
    float s = 0.f;
    #pragma unroll 8
    for (int c = 0; c < D; c++) {
        float x = e[c];
        s = fmaf(x, x, s);
        g_Eh[(size_t)k * D + c] = __float2half_rn(x * ESCL);  // normal-range fp16
    }
    g_normE[k] = s;
    red[threadIdx.x] = s;
    __syncthreads();
    for (int o = 64; o > 0; o >>= 1) {
        if (threadIdx.x < o) red[threadIdx.x] = fmaxf(red[threadIdx.x], red[threadIdx.x + o]);
        __syncthreads();
    }
    if (threadIdx.x == 0) g_maxEblk[blockIdx.x] = red[0];
}

// ---------------------------------------------------------------------------
// K1: transpose X -> token-major fp16 (coalesced via smem staging) + ||x||^2
// ---------------------------------------------------------------------------
__global__ void k_split_x(const float* __restrict__ X) {
    __shared__ float tile[D][33];
    __shared__ float psum[32][9];
    __shared__ uint4 hbuf[32][32];    // 32 tokens x 32 x 16B chunks (full rows)
    const int tid = threadIdx.x;
    const int b   = blockIdx.x >> 5;
    const int hw0 = (blockIdx.x & 31) * 32;
    const float* Xb = X + (size_t)b * (D * HW) + hw0;

    if (blockIdx.x == 0 && tid == 0) {       // finalize maxE (k_prep done: stream order)
        float m = 0.f;
        #pragma unroll
        for (int i = 0; i < 8; i++) m = fmaxf(m, g_maxEblk[i]);
        g_maxE = sqrtf(m);
    }
    if (tid < 32) g_cnt[b * HW + hw0 + tid] = 0;   // reset candidate counters

    {
        int w = tid >> 5, lane = tid & 31;
        #pragma unroll
        for (int c = w; c < D; c += 8) tile[c][lane] = Xb[(size_t)c * HW + lane];
    }
    __syncthreads();

    const int tt = tid >> 3;          // token 0..31
    const int cc = tid & 7;           // channel block (32 channels)
    float s = 0.f;
    #pragma unroll
    for (int c8 = 0; c8 < 4; c8++) {
        uint32_t hp[4];
        #pragma unroll
        for (int q = 0; q < 4; q++) {
            int c0 = cc * 32 + c8 * 8 + q * 2;
            float x0 = tile[c0][tt], x1 = tile[c0 + 1][tt];
            s = fmaf(x0, x0, s); s = fmaf(x1, x1, s);
            __half h0 = __float2half_rn(x0), h1 = __float2half_rn(x1);
            hp[q] = (uint32_t)*(uint16_t*)&h0 | ((uint32_t)*(uint16_t*)&h1 << 16);
        }
        hbuf[tt][cc * 4 + c8] = make_uint4(hp[0], hp[1], hp[2], hp[3]);
    }
    psum[tt][cc] = s;
    __syncthreads();

    // coalesced write: each warp stores one full 512B token row per iteration
    {
        const int w = tid >> 5, lane = tid & 31;
        uint4* dst = (uint4*)g_Xh;
        #pragma unroll
        for (int t = 0; t < 4; t++) {
            int token = t * 8 + w;
            dst[(size_t)(b * HW + hw0 + token) * 32 + lane] = hbuf[token][lane];
        }
    }
    if (cc == 0) {
        float t = 0.f;
        #pragma unroll
        for (int q = 0; q < 8; q++) t += psum[tt][q];
        g_normX[b * HW + hw0 + tt] = t;
    }
}

// ---------------------------------------------------------------------------
// K2: hh HMMA GEMM (K=256, E pre-scaled) + candidate collection in window
//   epilogue is atomics-free: shfl + slice-store + cross-slice reduce
// ---------------------------------------------------------------------------
__global__ void __launch_bounds__(256, 2) k_vq()
{
    extern __shared__ char smem[];                 // NSTG * (A 16KB | B 16KB)
    __shared__ float sliceMin[TM][4];
    __shared__ float bestS[TM];
    __shared__ float nXs[TM], nEs[TN];

    const int tid  = threadIdx.x;
    const int bid  = blockIdx.x;
    const int tokenBase = (bid >> 3) * TM;
    const int codeBase  = (bid & 7) * TN;

    if (tid < TM) {
        nXs[tid] = g_normX[tokenBase + tid];
        nEs[tid] = g_normE[codeBase + tid];
    }

    const uint32_t sb = smem_u32(smem);
    const int ldr = tid >> 3, lds = tid & 7;

    auto issue = [&](int s) {
        const int koff = s * KCH;
        const uint32_t Ab = sb + (s % NSTG) * STG_BYTES;
        const uint32_t Bb = Ab + 16384;
        #pragma unroll
        for (int i = 0; i < 4; i++) {
            int r = ldr + i * 32;
            uint32_t so = swaddr(r, lds);
            CP_ASYNC16(Ab + so, g_Xh + (size_t)(tokenBase + r) * D + koff + lds * 8);
            CP_ASYNC16(Bb + so, g_Eh + (size_t)(codeBase  + r) * D + koff + lds * 8);
        }
        CP_COMMIT();
    };

    issue(0); issue(1);

    const int lane = tid & 31, wid = tid >> 5;
    const int mrow0 = (wid & 1) * 64;
    const int ncol0 = (wid >> 1) * 32;
    const int lrow  = lane & 15, lhalf = lane >> 4;

    float acc[4][4][4];
    #pragma unroll
    for (int m = 0; m < 4; m++)
        #pragma unroll
        for (int n = 0; n < 4; n++)
            #pragma unroll
            for (int q = 0; q < 4; q++) acc[m][n][q] = 0.f;

    for (int s = 0; s < NITER; s++) {
        CP_WAIT1();
        __syncthreads();
        if (s + 2 < NITER) issue(s + 2);

        const uint32_t Ab = sb + (s % NSTG) * STG_BYTES;
        const uint32_t Bb = Ab + 16384;

        #pragma unroll
        for (int k16 = 0; k16 < 4; k16++) {
            const int u = k16 * 2 + lhalf;
            uint32_t a[4][4], bfr[2][4];
            #pragma unroll
            for (int m = 0; m < 4; m++) {
                int r = mrow0 + m * 16 + lrow;
                LDSM_X4(a[m][0], a[m][1], a[m][2], a[m][3], Ab + swaddr(r, u));
            }
            #pragma unroll
            for (int nb = 0; nb < 2; nb++) {
                int r = ncol0 + nb * 16 + lrow;
                LDSM_X4(bfr[nb][0], bfr[nb][1], bfr[nb][2], bfr[nb][3], Bb + swaddr(r, u));
            }
            #pragma unroll
            for (int m = 0; m < 4; m++)
                #pragma unroll
                for (int n = 0; n < 4; n++)
                    MMA_F16(acc[m][n], a[m], bfr[n >> 1][n & 1], bfr[n >> 1][2 + (n & 1)]);
        }
    }

    // ---- pass 1: distances into acc + per-row CTA min (no atomics)
    #pragma unroll
    for (int m = 0; m < 4; m++) {
        #pragma unroll
        for (int rr = 0; rr < 2; rr++) {
            const int row = mrow0 + m * 16 + (lane >> 2) + rr * 8;
            const float nX = nXs[row];
            float dmin = CUDART_INF_F;
            #pragma unroll
            for (int n = 0; n < 4; n++) {
                #pragma unroll
                for (int cc2 = 0; cc2 < 2; cc2++) {
                    const int col = ncol0 + n * 8 + 2 * (lane & 3) + cc2;
                    float sdot = __fmul_rn(acc[m][n][rr * 2 + cc2], ESCL_INV); // exact
                    float d = __fadd_rn(__fsub_rn(nX, __fmul_rn(2.0f, sdot)), nEs[col]);
                    acc[m][n][rr * 2 + cc2] = d;      // keep for pass 2
                    dmin = fminf(dmin, d);
                }
            }
            dmin = fminf(dmin, __shfl_xor_sync(0xFFFFFFFFu, dmin, 1));
            dmin = fminf(dmin, __shfl_xor_sync(0xFFFFFFFFu, dmin, 2));
            if ((lane & 3) == 0) sliceMin[row][wid >> 1] = dmin;
        }
    }
    __syncthreads();
    if (tid < TM) {
        bestS[tid] = fminf(fminf(sliceMin[tid][0], sliceMin[tid][1]),
                           fminf(sliceMin[tid][2], sliceMin[tid][3]));
    }
    __syncthreads();

    // ---- pass 2: append candidates within 2T of CTA-local min
    const float mE = g_maxE;
    #pragma unroll
    for (int m = 0; m < 4; m++) {
        #pragma unroll
        for (int rr = 0; rr < 2; rr++) {
            const int row = mrow0 + m * 16 + (lane >> 2) + rr * 8;
            const float nX = nXs[row];
            const float T = fmaf(T_COEF * sqrtf(nX), mE, T_SLACK);
            const float thr = bestS[row] + 2.0f * T;
            const int nglob = tokenBase + row;
            #pragma unroll
            for (int n = 0; n < 4; n++) {
                #pragma unroll
                for (int cc2 = 0; cc2 < 2; cc2++) {
                    float d = acc[m][n][rr * 2 + cc2];
                    if (d <= thr) {
                        const int col = ncol0 + n * 8 + 2 * (lane & 3) + cc2;
                        int slot = atomicAdd(&g_cnt[nglob], 1);
                        if (slot < CAND_CAP)
                            g_cand[(size_t)nglob * CAND_CAP + slot] =
                                ((unsigned long long)__float_as_uint(d) << 32) |
                                (unsigned)(codeBase + col);
                    }
                }
            }
        }
    }
}

// ---------------------------------------------------------------------------
// K3: exact refine — warp per token; x row in registers (loaded on demand)
// ---------------------------------------------------------------------------
__global__ void k_refine(const float* __restrict__ E, const float* __restrict__ X)
{
    const int lane = threadIdx.x & 31;
    const int w    = threadIdx.x >> 5;
    const int n = blockIdx.x * 8 + w;
    const float nX = g_normX[n];
    const float T = fmaf(T_COEF * sqrtf(nX), g_maxE, T_SLACK);
    const int cnt = g_cnt[n];
    unsigned long long best = ~0ull;

    const int b  = n >> 10;
    const int hw = n & (HW - 1);
    const float* xsrc = X + (size_t)b * (D * HW) + hw;

    if (cnt <= CAND_CAP) {
        unsigned long long c = (lane < cnt) ? g_cand[(size_t)n * CAND_CAP + lane] : ~0ull;
        unsigned long long mn = c;
        #pragma unroll
        for (int o = 16; o > 0; o >>= 1) {
            unsigned long long t = __shfl_xor_sync(0xFFFFFFFFu, mn, o);
            mn = (t < mn) ? t : mn;
        }
        const float dmin = __uint_as_float((uint32_t)(mn >> 32));
        const float thr = dmin + 2.0f * T;
        const bool keep = (lane < cnt) &&
                          (__uint_as_float((uint32_t)(c >> 32)) <= thr);
        unsigned mask = __ballot_sync(0xFFFFFFFFu, keep);
        if (__popc(mask) == 1) {
            best = mn;                      // unique candidate: provably the argmin
        } else {
            float xr[8];
            #pragma unroll
            for (int j = 0; j < 8; j++)
                xr[j] = xsrc[(size_t)(lane * 8 + j) * HW];
            unsigned mm = mask;
            while (mm) {
                int bb = __ffs(mm) - 1; mm &= mm - 1;
                int kk = (int)__shfl_sync(0xFFFFFFFFu, (unsigned)(c & 0xFFFFFFFFu), bb);
                const float* er = E + (size_t)kk * D;
                float p = 0.f;
                #pragma unroll
                for (int j = 0; j < 8; j++)
                    p = fmaf(xr[j], er[lane * 8 + j], p);
                #pragma unroll
                for (int o = 16; o > 0; o >>= 1) p += __shfl_xor_sync(0xFFFFFFFFu, p, o);
                float d = __fadd_rn(__fsub_rn(nX, __fmul_rn(2.0f, p)), g_normE[kk]);
                unsigned long long key =
                    ((unsigned long long)__float_as_uint(d) << 32) | (unsigned)kk;
                best = (key < best) ? key : best;
            }
        }
    } else {
        // overflow fallback: exact cooperative full scan (essentially never taken)
        float xr[8];
        #pragma unroll
        for (int j = 0; j < 8; j++)
            xr[j] = xsrc[(size_t)(lane * 8 + j) * HW];
        for (int k0 = 0; k0 < K; k0++) {
            const float* er = E + (size_t)k0 * D;
            float p = 0.f;
            #pragma unroll
            for (int j = 0; j < 8; j++)
                p = fmaf(xr[j], er[lane * 8 + j], p);
            #pragma unroll
            for (int o = 16; o > 0; o >>= 1) p += __shfl_xor_sync(0xFFFFFFFFu, p, o);
            float d = __fadd_rn(__fsub_rn(nX, __fmul_rn(2.0f, p)), g_normE[k0]);
            unsigned long long key =
                ((unsigned long long)__float_as_uint(d) << 32) | (unsigned)k0;
            best = (key < best) ? key : best;
        }
    }
    if (lane == 0) g_idx[n] = (int)(best & 0xFFFFFFFFu);
}

// ---------------------------------------------------------------------------
// K4: gather (with reference x+(q-x) rounding) + idx out + MSE partials
// ---------------------------------------------------------------------------
__global__ void k_gather(const float* __restrict__ X, const float* __restrict__ E,
                         float* __restrict__ Q, int writeQ,
                         float* __restrict__ outIdxF, int writeIdx)
{
    __shared__ double sred[256];
    const int tid = threadIdx.x;
    const int cb  = blockIdx.x >> 7;
    const int n   = (blockIdx.x & 127) * 256 + tid;
    const int b   = n >> 10;
    const int hw  = n & (HW - 1);
    const int ch0 = cb * 32;
    const float* xb = X + (size_t)b * (D * HW) + (size_t)ch0 * HW + hw;
    float*       qb = Q + (size_t)b * (D * HW) + (size_t)ch0 * HW + hw;
    const int idx = g_idx[n];
    const float* e = E + (size_t)idx * D + ch0;

    if (writeIdx && cb == 0) outIdxF[n] = (float)idx;

    double s = 0.0;
    #pragma unroll
    for (int c4 = 0; c4 < 8; c4++) {
        float4 q4 = *(const float4*)(e + c4 * 4);
        float qv[4] = {q4.x, q4.y, q4.z, q4.w};
        #pragma unroll
        for (int j = 0; j < 4; j++) {
            int c = c4 * 4 + j;
            float x = xb[(size_t)c * HW];
            float dd = __fsub_rn(qv[j], x);
            if (writeQ) qb[(size_t)c * HW] = __fadd_rn(x, dd);   // ref straight-through
            s = fma((double)dd, (double)dd, s);
        }
    }
    sred[tid] = s;
    __syncthreads();
    for (int off = 128; off > 0; off >>= 1) {
        if (tid < off) sred[tid] += sred[tid + off];
        __syncthreads();
    }
    if (tid == 0) g_partial[blockIdx.x] = sred[0];
}

__global__ void k_loss(float* __restrict__ out, int lossOff)
{
    __shared__ double sd[256];
    int t = threadIdx.x;
    double s = 0.0;
    #pragma unroll
    for (int i = 0; i < 4; i++) s += g_partial[t * 4 + i];
    sd[t] = s;
    __syncthreads();
    for (int o = 128; o > 0; o >>= 1) {
        if (t < o) sd[t] += sd[t + o];
        __syncthreads();
    }
    if (t == 0) {
        float e = (float)(sd[0] / (double)((size_t)NTOK * D));
        out[lossOff] = e + 0.25f * e;
    }
}

// ---------------------------------------------------------------------------
extern "C" void kernel_launch(void* const* d_in, const int* in_sizes, int n_in,
                              void* d_out, int out_size)
{
    const float* X = (const float*)d_in[0];   // [32,256,32,32]
    const float* E = (const float*)d_in[1];   // [1024,256]
    float* out = (float*)d_out;

    const int qn = NTOK * D;
    int writeQ = 0, lossOff = -1, idxOff = -1;
    if (out_size >= qn) writeQ = 1;
    if (out_size == qn + 1 + NTOK) { lossOff = qn; idxOff = qn + 1; }
    else if (out_size == qn + 1)   { lossOff = qn; }
    else if (out_size == qn + NTOK){ idxOff = qn; }
    else if (out_size == NTOK)     { idxOff = 0; writeQ = 0; }

    cudaFuncSetAttribute(k_vq, cudaFuncAttributeMaxDynamicSharedMemorySize,
                         NSTG * STG_BYTES);

    k_prep_e<<<8, 128>>>(E);
    k_split_x<<<NTOK / 32, 256>>>(X);
    k_vq<<<(NTOK / TM) * (K / TN), 256, NSTG * STG_BYTES>>>();
    k_refine<<<NTOK / 8, 256>>>(E, X);
    k_gather<<<1024, 256>>>(X, E, out, writeQ,
                            (idxOff >= 0) ? (out + idxOff) : out,
                            (idxOff >= 0) ? 1 : 0);
    if (lossOff >= 0)
        k_loss<<<1, 256>>>(out, lossOff);
}

// round 10
// speedup vs baseline: 1.0029x; 1.0029x over previous
#include <cuda_runtime.h>
#include <cuda_fp16.h>
#include <math_constants.h>
#include <cstdint>

// ---------------- problem constants ----------------
#define NTOK 32768      // 32*32*32 tokens
#define D    256        // embedding dim
#define K    1024       // codebook size
#define HW   1024       // H*W
#define TM   128        // tokens per CTA tile
#define TN   128        // codes per CTA tile
#define KCH  64         // dims per pipeline stage
#define NITER 4         // 4 chunks of 64 dims (hh only)
#define NSTG 3          // cp.async stages
#define STG_BYTES 32768 // A 16KB + B 16KB per stage
#define CAND_CAP 32
#define ESCL      1024.0f          // 2^10 exact
#define ESCL_INV  9.765625e-4f     // 2^-10 exact
// |d_hh - d_exact| <= 4*2^-11*||x||*||e||max + slack
#define T_COEF  1.98e-3f
#define T_SLACK 2.0e-4f

// ---------------- device scratch (no allocations allowed) ----------------
__device__ __align__(256) __half g_Xh[NTOK * D];
__device__ __align__(256) __half g_Eh[K * D];      // fl16(e * 2^10)
__device__ float  g_normX[NTOK];
__device__ float  g_normE[K];
__device__ float  g_maxEblk[8];
__device__ float  g_maxE;
__device__ int    g_cnt[NTOK];
__device__ unsigned long long g_cand[NTOK * CAND_CAP];
__device__ int    g_idx[NTOK];
__device__ double g_partial[1024];

__device__ __forceinline__ uint32_t smem_u32(const void* p) {
    uint32_t a;
    asm("{ .reg .u64 t; cvta.to.shared.u64 t, %1; cvt.u32.u64 %0, t; }" : "=r"(a) : "l"(p));
    return a;
}
#define CP_ASYNC16(saddr, gptr) \
    asm volatile("cp.async.cg.shared.global [%0], [%1], 16;" :: "r"(saddr), "l"(gptr))
#define CP_COMMIT() asm volatile("cp.async.commit_group;" ::: "memory")
#define CP_WAIT1()  asm volatile("cp.async.wait_group 1;" ::: "memory")
#define LDSM_X4(r0, r1, r2, r3, a) \
    asm volatile("ldmatrix.sync.aligned.m8n8.x4.shared.b16 {%0,%1,%2,%3}, [%4];" \
        : "=r"(r0), "=r"(r1), "=r"(r2), "=r"(r3) : "r"(a))
#define MMA_F16(d, a, b0v, b1v) \
    asm volatile("mma.sync.aligned.m16n8k16.row.col.f32.f16.f16.f32 " \
        "{%0,%1,%2,%3}, {%4,%5,%6,%7}, {%8,%9}, {%0,%1,%2,%3};" \
        : "+f"((d)[0]), "+f"((d)[1]), "+f"((d)[2]), "+f"((d)[3]) \
        : "r"((a)[0]), "r"((a)[1]), "r"((a)[2]), "r"((a)[3]), "r"(b0v), "r"(b1v))

__device__ __forceinline__ uint32_t swaddr(int row, int u) {
    return (uint32_t)(row * 128 + ((u ^ (row & 7)) << 4));
}

// ---------------------------------------------------------------------------
// K0: codebook fp16 (pre-scaled by 2^10) + squared norms + per-block max norm
// ---------------------------------------------------------------------------
__global__ void k_prep_e(const float* __restrict__ E) {
    __shared__ float red[128];
    int k = blockIdx.x * blockDim.x + threadIdx.x;
    const float* e = E + (size_t)k * D;
    float s = 0.f;
    #pragma unroll 8
    for (int c = 0; c < D; c++) {
        float x = e[c];
        s = fmaf(x, x, s);
        g_Eh[(size_t)k * D + c] = __float2half_rn(x * ESCL);  // normal-range fp16
    }
    g_normE[k] = s;
    red[threadIdx.x] = s;
    __syncthreads();
    for (int o = 64; o > 0; o >>= 1) {
        if (threadIdx.x < o) red[threadIdx.x] = fmaxf(red[threadIdx.x], red[threadIdx.x + o]);
        __syncthreads();
    }
    if (threadIdx.x == 0) g_maxEblk[blockIdx.x] = red[0];
}

// ---------------------------------------------------------------------------
// K1: transpose X -> token-major fp16 (coalesced via smem staging) + ||x||^2
// ---------------------------------------------------------------------------
__global__ void k_split_x(const float* __restrict__ X) {
    __shared__ float tile[D][33];
    __shared__ float psum[32][9];
    __shared__ uint4 hbuf[32][32];    // 32 tokens x 32 x 16B chunks (full rows)
    const int tid = threadIdx.x;
    const int b   = blockIdx.x >> 5;
    const int hw0 = (blockIdx.x & 31) * 32;
    const float* Xb = X + (size_t)b * (D * HW) + hw0;

    if (blockIdx.x == 0 && tid == 0) {       // finalize maxE (k_prep done: stream order)
        float m = 0.f;
        #pragma unroll
        for (int i = 0; i < 8; i++) m = fmaxf(m, g_maxEblk[i]);
        g_maxE = sqrtf(m);
    }
    if (tid < 32) g_cnt[b * HW + hw0 + tid] = 0;   // reset candidate counters

    {
        int w = tid >> 5, lane = tid & 31;
        #pragma unroll
        for (int c = w; c < D; c += 8) tile[c][lane] = Xb[(size_t)c * HW + lane];
    }
    __syncthreads();

    const int tt = tid >> 3;          // token 0..31
    const int cc = tid & 7;           // channel block (32 channels)
    float s = 0.f;
    #pragma unroll
    for (int c8 = 0; c8 < 4; c8++) {
        uint32_t hp[4];
        #pragma unroll
        for (int q = 0; q < 4; q++) {
            int c0 = cc * 32 + c8 * 8 + q * 2;
            float x0 = tile[c0][tt], x1 = tile[c0 + 1][tt];
            s = fmaf(x0, x0, s); s = fmaf(x1, x1, s);
            __half h0 = __float2half_rn(x0), h1 = __float2half_rn(x1);
            hp[q] = (uint32_t)*(uint16_t*)&h0 | ((uint32_t)*(uint16_t*)&h1 << 16);
        }
        hbuf[tt][cc * 4 + c8] = make_uint4(hp[0], hp[1], hp[2], hp[3]);
    }
    psum[tt][cc] = s;
    __syncthreads();

    // coalesced write: each warp stores one full 512B token row per iteration
    {
        const int w = tid >> 5, lane = tid & 31;
        uint4* dst = (uint4*)g_Xh;
        #pragma unroll
        for (int t = 0; t < 4; t++) {
            int token = t * 8 + w;
            dst[(size_t)(b * HW + hw0 + token) * 32 + lane] = hbuf[token][lane];
        }
    }
    if (cc == 0) {
        float t = 0.f;
        #pragma unroll
        for (int q = 0; q < 8; q++) t += psum[tt][q];
        g_normX[b * HW + hw0 + tt] = t;
    }
}

// ---------------------------------------------------------------------------
// K2: hh HMMA GEMM (K=256, E pre-scaled) + candidate collection in window
//   epilogue is atomics-free: shfl + slice-store + cross-slice reduce
// ---------------------------------------------------------------------------
__global__ void __launch_bounds__(256, 2) k_vq()
{
    extern __shared__ char smem[];                 // NSTG * (A 16KB | B 16KB)
    __shared__ float sliceMin[TM][4];
    __shared__ float bestS[TM];
    __shared__ float nXs[TM], nEs[TN];

    const int tid  = threadIdx.x;
    const int bid  = blockIdx.x;
    const int tokenBase = (bid >> 3) * TM;
    const int codeBase  = (bid & 7) * TN;

    if (tid < TM) {
        nXs[tid] = g_normX[tokenBase + tid];
        nEs[tid] = g_normE[codeBase + tid];
    }

    const uint32_t sb = smem_u32(smem);
    const int ldr = tid >> 3, lds = tid & 7;

    auto issue = [&](int s) {
        const int koff = s * KCH;
        const uint32_t Ab = sb + (s % NSTG) * STG_BYTES;
        const uint32_t Bb = Ab + 16384;
        #pragma unroll
        for (int i = 0; i < 4; i++) {
            int r = ldr + i * 32;
            uint32_t so = swaddr(r, lds);
            CP_ASYNC16(Ab + so, g_Xh + (size_t)(tokenBase + r) * D + koff + lds * 8);
            CP_ASYNC16(Bb + so, g_Eh + (size_t)(codeBase  + r) * D + koff + lds * 8);
        }
        CP_COMMIT();
    };

    issue(0); issue(1);

    const int lane = tid & 31, wid = tid >> 5;
    const int mrow0 = (wid & 1) * 64;
    const int ncol0 = (wid >> 1) * 32;
    const int lrow  = lane & 15, lhalf = lane >> 4;

    float acc[4][4][4];
    #pragma unroll
    for (int m = 0; m < 4; m++)
        #pragma unroll
        for (int n = 0; n < 4; n++)
            #pragma unroll
            for (int q = 0; q < 4; q++) acc[m][n][q] = 0.f;

    for (int s = 0; s < NITER; s++) {
        CP_WAIT1();
        __syncthreads();
        if (s + 2 < NITER) issue(s + 2);

        const uint32_t Ab = sb + (s % NSTG) * STG_BYTES;
        const uint32_t Bb = Ab + 16384;

        #pragma unroll
        for (int k16 = 0; k16 < 4; k16++) {
            const int u = k16 * 2 + lhalf;
            uint32_t a[4][4], bfr[2][4];
            #pragma unroll
            for (int m = 0; m < 4; m++) {
                int r = mrow0 + m * 16 + lrow;
                LDSM_X4(a[m][0], a[m][1], a[m][2], a[m][3], Ab + swaddr(r, u));
            }
            #pragma unroll
            for (int nb = 0; nb < 2; nb++) {
                int r = ncol0 + nb * 16 + lrow;
                LDSM_X4(bfr[nb][0], bfr[nb][1], bfr[nb][2], bfr[nb][3], Bb + swaddr(r, u));
            }
            #pragma unroll
            for (int m = 0; m < 4; m++)
                #pragma unroll
                for (int n = 0; n < 4; n++)
                    MMA_F16(acc[m][n], a[m], bfr[n >> 1][n & 1], bfr[n >> 1][2 + (n & 1)]);
        }
    }

    // ---- pass 1: distances into acc + per-row CTA min (no atomics)
    #pragma unroll
    for (int m = 0; m < 4; m++) {
        #pragma unroll
        for (int rr = 0; rr < 2; rr++) {
            const int row = mrow0 + m * 16 + (lane >> 2) + rr * 8;
            const float nX = nXs[row];
            float dmin = CUDART_INF_F;
            #pragma unroll
            for (int n = 0; n < 4; n++) {
                #pragma unroll
                for (int cc2 = 0; cc2 < 2; cc2++) {
                    const int col = ncol0 + n * 8 + 2 * (lane & 3) + cc2;
                    float sdot = __fmul_rn(acc[m][n][rr * 2 + cc2], ESCL_INV); // exact
                    float d = __fadd_rn(__fsub_rn(nX, __fmul_rn(2.0f, sdot)), nEs[col]);
                    acc[m][n][rr * 2 + cc2] = d;      // keep for pass 2
                    dmin = fminf(dmin, d);
                }
            }
            dmin = fminf(dmin, __shfl_xor_sync(0xFFFFFFFFu, dmin, 1));
            dmin = fminf(dmin, __shfl_xor_sync(0xFFFFFFFFu, dmin, 2));
            if ((lane & 3) == 0) sliceMin[row][wid >> 1] = dmin;
        }
    }
    __syncthreads();
    if (tid < TM) {
        bestS[tid] = fminf(fminf(sliceMin[tid][0], sliceMin[tid][1]),
                           fminf(sliceMin[tid][2], sliceMin[tid][3]));
    }
    __syncthreads();

    // ---- pass 2: append candidates within 2T of CTA-local min
    const float mE = g_maxE;
    #pragma unroll
    for (int m = 0; m < 4; m++) {
        #pragma unroll
        for (int rr = 0; rr < 2; rr++) {
            const int row = mrow0 + m * 16 + (lane >> 2) + rr * 8;
            const float nX = nXs[row];
            const float T = fmaf(T_COEF * sqrtf(nX), mE, T_SLACK);
            const float thr = bestS[row] + 2.0f * T;
            const int nglob = tokenBase + row;
            #pragma unroll
            for (int n = 0; n < 4; n++) {
                #pragma unroll
                for (int cc2 = 0; cc2 < 2; cc2++) {
                    float d = acc[m][n][rr * 2 + cc2];
                    if (d <= thr) {
                        const int col = ncol0 + n * 8 + 2 * (lane & 3) + cc2;
                        int slot = atomicAdd(&g_cnt[nglob], 1);
                        if (slot < CAND_CAP)
                            g_cand[(size_t)nglob * CAND_CAP + slot] =
                                ((unsigned long long)__float_as_uint(d) << 32) |
                                (unsigned)(codeBase + col);
                    }
                }
            }
        }
    }
}

// ---------------------------------------------------------------------------
// K3: exact refine — warp per token; x row in registers (loaded on demand)
// ---------------------------------------------------------------------------
__global__ void k_refine(const float* __restrict__ E, const float* __restrict__ X)
{
    const int lane = threadIdx.x & 31;
    const int w    = threadIdx.x >> 5;
    const int n = blockIdx.x * 8 + w;
    const float nX = g_normX[n];
    const float T = fmaf(T_COEF * sqrtf(nX), g_maxE, T_SLACK);
    const int cnt = g_cnt[n];
    unsigned long long best = ~0ull;

    const int b  = n >> 10;
    const int hw = n & (HW - 1);
    const float* xsrc = X + (size_t)b * (D * HW) + hw;

    if (cnt <= CAND_CAP) {
        unsigned long long c = (lane < cnt) ? g_cand[(size_t)n * CAND_CAP + lane] : ~0ull;
        unsigned long long mn = c;
        #pragma unroll
        for (int o = 16; o > 0; o >>= 1) {
            unsigned long long t = __shfl_xor_sync(0xFFFFFFFFu, mn, o);
            mn = (t < mn) ? t : mn;
        }
        const float dmin = __uint_as_float((uint32_t)(mn >> 32));
        const float thr = dmin + 2.0f * T;
        const bool keep = (lane < cnt) &&
                          (__uint_as_float((uint32_t)(c >> 32)) <= thr);
        unsigned mask = __ballot_sync(0xFFFFFFFFu, keep);
        if (__popc(mask) == 1) {
            best = mn;                      // unique candidate: provably the argmin
        } else {
            float xr[8];
            #pragma unroll
            for (int j = 0; j < 8; j++)
                xr[j] = xsrc[(size_t)(lane * 8 + j) * HW];
            unsigned mm = mask;
            while (mm) {
                int bb = __ffs(mm) - 1; mm &= mm - 1;
                int kk = (int)__shfl_sync(0xFFFFFFFFu, (unsigned)(c & 0xFFFFFFFFu), bb);
                const float* er = E + (size_t)kk * D;
                float p = 0.f;
                #pragma unroll
                for (int j = 0; j < 8; j++)
                    p = fmaf(xr[j], er[lane * 8 + j], p);
                #pragma unroll
                for (int o = 16; o > 0; o >>= 1) p += __shfl_xor_sync(0xFFFFFFFFu, p, o);
                float d = __fadd_rn(__fsub_rn(nX, __fmul_rn(2.0f, p)), g_normE[kk]);
                unsigned long long key =
                    ((unsigned long long)__float_as_uint(d) << 32) | (unsigned)kk;
                best = (key < best) ? key : best;
            }
        }
    } else {
        // overflow fallback: exact cooperative full scan (essentially never taken)
        float xr[8];
        #pragma unroll
        for (int j = 0; j < 8; j++)
            xr[j] = xsrc[(size_t)(lane * 8 + j) * HW];
        for (int k0 = 0; k0 < K; k0++) {
            const float* er = E + (size_t)k0 * D;
            float p = 0.f;
            #pragma unroll
            for (int j = 0; j < 8; j++)
                p = fmaf(xr[j], er[lane * 8 + j], p);
            #pragma unroll
            for (int o = 16; o > 0; o >>= 1) p += __shfl_xor_sync(0xFFFFFFFFu, p, o);
            float d = __fadd_rn(__fsub_rn(nX, __fmul_rn(2.0f, p)), g_normE[k0]);
            unsigned long long key =
                ((unsigned long long)__float_as_uint(d) << 32) | (unsigned)k0;
            best = (key < best) ? key : best;
        }
    }
    if (lane == 0) g_idx[n] = (int)(best & 0xFFFFFFFFu);
}

// ---------------------------------------------------------------------------
// K4: gather (with reference x+(q-x) rounding) + idx out + MSE partials
// ---------------------------------------------------------------------------
__global__ void k_gather(const float* __restrict__ X, const float* __restrict__ E,
                         float* __restrict__ Q, int writeQ,
                         float* __restrict__ outIdxF, int writeIdx)
{
    __shared__ double sred[256];
    const int tid = threadIdx.x;
    const int cb  = blockIdx.x >> 7;
    const int n   = (blockIdx.x & 127) * 256 + tid;
    const int b   = n >> 10;
    const int hw  = n & (HW - 1);
    const int ch0 = cb * 32;
    const float* xb = X + (size_t)b * (D * HW) + (size_t)ch0 * HW + hw;
    float*       qb = Q + (size_t)b * (D * HW) + (size_t)ch0 * HW + hw;
    const int idx = g_idx[n];
    const float* e = E + (size_t)idx * D + ch0;

    if (writeIdx && cb == 0) outIdxF[n] = (float)idx;

    double s = 0.0;
    #pragma unroll
    for (int c4 = 0; c4 < 8; c4++) {
        float4 q4 = *(const float4*)(e + c4 * 4);
        float qv[4] = {q4.x, q4.y, q4.z, q4.w};
        #pragma unroll
        for (int j = 0; j < 4; j++) {
            int c = c4 * 4 + j;
            float x = xb[(size_t)c * HW];
            float dd = __fsub_rn(qv[j], x);
            if (writeQ) qb[(size_t)c * HW] = __fadd_rn(x, dd);   // ref straight-through
            s = fma((double)dd, (double)dd, s);
        }
    }
    sred[tid] = s;
    __syncthreads();
    for (int off = 128; off > 0; off >>= 1) {
        if (tid < off) sred[tid] += sred[tid + off];
        __syncthreads();
    }
    if (tid == 0) g_partial[blockIdx.x] = sred[0];
}

__global__ void k_loss(float* __restrict__ out, int lossOff)
{
    __shared__ double sd[256];
    int t = threadIdx.x;
    double s = 0.0;
    #pragma unroll
    for (int i = 0; i < 4; i++) s += g_partial[t * 4 + i];
    sd[t] = s;
    __syncthreads();
    for (int o = 128; o > 0; o >>= 1) {
        if (t < o) sd[t] += sd[t + o];
        __syncthreads();
    }
    if (t == 0) {
        float e = (float)(sd[0] / (double)((size_t)NTOK * D));
        out[lossOff] = e + 0.25f * e;
    }
}

// ---------------------------------------------------------------------------
extern "C" void kernel_launch(void* const* d_in, const int* in_sizes, int n_in,
                              void* d_out, int out_size)
{
    const float* X = (const float*)d_in[0];   // [32,256,32,32]
    const float* E = (const float*)d_in[1];   // [1024,256]
    float* out = (float*)d_out;

    const int qn = NTOK * D;
    int writeQ = 0, lossOff = -1, idxOff = -1;
    if (out_size >= qn) writeQ = 1;
    if (out_size == qn + 1 + NTOK) { lossOff = qn; idxOff = qn + 1; }
    else if (out_size == qn + 1)   { lossOff = qn; }
    else if (out_size == qn + NTOK){ idxOff = qn; }
    else if (out_size == NTOK)     { idxOff = 0; writeQ = 0; }

    cudaFuncSetAttribute(k_vq, cudaFuncAttributeMaxDynamicSharedMemorySize,
                         NSTG * STG_BYTES);

    k_prep_e<<<8, 128>>>(E);
    k_split_x<<<NTOK / 32, 256>>>(X);
    k_vq<<<(NTOK / TM) * (K / TN), 256, NSTG * STG_BYTES>>>();
    k_refine<<<NTOK / 8, 256>>>(E, X);
    k_gather<<<1024, 256>>>(X, E, out, writeQ,
                            (idxOff >= 0) ? (out + idxOff) : out,
                            (idxOff >= 0) ? 1 : 0);
    if (lossOff >= 0)
        k_loss<<<1, 256>>>(out, lossOff);
}

// round 11
// speedup vs baseline: 1.1441x; 1.1408x over previous
#include <cuda_runtime.h>
#include <cuda_fp16.h>
#include <math_constants.h>
#include <cstdint>

// ---------------- problem constants ----------------
#define NTOK 32768      // 32*32*32 tokens
#define D    256        // embedding dim
#define K    1024       // codebook size
#define HW   1024       // H*W
#define TM   128        // tokens per CTA tile
#define TN   128        // codes per chunk
#define KCH  64         // dims per pipeline stage
#define NCHUNK 8        // K / TN
#define NSTAGE 32       // NCHUNK * (D/KCH)
#define NSTG 3          // cp.async B-stage ring
#define B_STG 16384     // 128 codes x 64 dims x 2B
#define A_BYTES 65536   // 128 tokens x 256 dims x 2B
#define SMEM_DYN (A_BYTES + NSTG * B_STG)   // 114688
#define CAND_CAP 32
#define ESCL      1024.0f          // 2^10 exact
#define ESCL_INV  9.765625e-4f     // 2^-10 exact
// |d_hh - d_exact| <= 4*2^-11*||x||*||e||max + slack
#define T_COEF  1.98e-3f
#define T_SLACK 2.0e-4f

// ---------------- device scratch (no allocations allowed) ----------------
__device__ __align__(256) __half g_Xh[NTOK * D];
__device__ __align__(256) __half g_Eh[K * D];      // fl16(e * 2^10)
__device__ float  g_normX[NTOK];
__device__ float  g_normE[K];
__device__ float  g_maxEblk[8];
__device__ float  g_maxE;
__device__ int    g_cnt[NTOK];
__device__ unsigned long long g_cand[NTOK * CAND_CAP];
__device__ int    g_idx[NTOK];
__device__ double g_partial[1024];

__device__ __forceinline__ uint32_t smem_u32(const void* p) {
    uint32_t a;
    asm("{ .reg .u64 t; cvta.to.shared.u64 t, %1; cvt.u32.u64 %0, t; }" : "=r"(a) : "l"(p));
    return a;
}
#define CP_ASYNC16(saddr, gptr) \
    asm volatile("cp.async.cg.shared.global [%0], [%1], 16;" :: "r"(saddr), "l"(gptr))
#define CP_COMMIT() asm volatile("cp.async.commit_group;" ::: "memory")
#define CP_WAIT1()  asm volatile("cp.async.wait_group 1;" ::: "memory")
#define LDSM_X4(r0, r1, r2, r3, a) \
    asm volatile("ldmatrix.sync.aligned.m8n8.x4.shared.b16 {%0,%1,%2,%3}, [%4];" \
        : "=r"(r0), "=r"(r1), "=r"(r2), "=r"(r3) : "r"(a))
#define MMA_F16(d, a, b0v, b1v) \
    asm volatile("mma.sync.aligned.m16n8k16.row.col.f32.f16.f16.f32 " \
        "{%0,%1,%2,%3}, {%4,%5,%6,%7}, {%8,%9}, {%0,%1,%2,%3};" \
        : "+f"((d)[0]), "+f"((d)[1]), "+f"((d)[2]), "+f"((d)[3]) \
        : "r"((a)[0]), "r"((a)[1]), "r"((a)[2]), "r"((a)[3]), "r"(b0v), "r"(b1v))

__device__ __forceinline__ uint32_t swaddr(int row, int u) {
    return (uint32_t)(row * 128 + ((u ^ (row & 7)) << 4));
}

// ---------------------------------------------------------------------------
// K0: codebook fp16 (pre-scaled by 2^10) + squared norms + per-block max norm
// ---------------------------------------------------------------------------
__global__ void k_prep_e(const float* __restrict__ E) {
    __shared__ float red[128];
    int k = blockIdx.x * blockDim.x + threadIdx.x;
    const float* e = E + (size_t)k * D;
    float s = 0.f;
    #pragma unroll 8
    for (int c = 0; c < D; c++) {
        float x = e[c];
        s = fmaf(x, x, s);
        g_Eh[(size_t)k * D + c] = __float2half_rn(x * ESCL);  // normal-range fp16
    }
    g_normE[k] = s;
    red[threadIdx.x] = s;
    __syncthreads();
    for (int o = 64; o > 0; o >>= 1) {
        if (threadIdx.x < o) red[threadIdx.x] = fmaxf(red[threadIdx.x], red[threadIdx.x + o]);
        __syncthreads();
    }
    if (threadIdx.x == 0) g_maxEblk[blockIdx.x] = red[0];
}

// ---------------------------------------------------------------------------
// K1: transpose X -> token-major fp16 (coalesced via smem staging) + ||x||^2
// ---------------------------------------------------------------------------
__global__ void k_split_x(const float* __restrict__ X) {
    __shared__ float tile[D][33];
    __shared__ float psum[32][9];
    __shared__ uint4 hbuf[32][32];    // 32 tokens x 32 x 16B chunks (full rows)
    const int tid = threadIdx.x;
    const int b   = blockIdx.x >> 5;
    const int hw0 = (blockIdx.x & 31) * 32;
    const float* Xb = X + (size_t)b * (D * HW) + hw0;

    if (blockIdx.x == 0 && tid == 0) {       // finalize maxE (k_prep done: stream order)
        float m = 0.f;
        #pragma unroll
        for (int i = 0; i < 8; i++) m = fmaxf(m, g_maxEblk[i]);
        g_maxE = sqrtf(m);
    }
    if (tid < 32) g_cnt[b * HW + hw0 + tid] = 0;   // reset candidate counters

    {
        int w = tid >> 5, lane = tid & 31;
        #pragma unroll
        for (int c = w; c < D; c += 8) tile[c][lane] = Xb[(size_t)c * HW + lane];
    }
    __syncthreads();

    const int tt = tid >> 3;          // token 0..31
    const int cc = tid & 7;           // channel block (32 channels)
    float s = 0.f;
    #pragma unroll
    for (int c8 = 0; c8 < 4; c8++) {
        uint32_t hp[4];
        #pragma unroll
        for (int q = 0; q < 4; q++) {
            int c0 = cc * 32 + c8 * 8 + q * 2;
            float x0 = tile[c0][tt], x1 = tile[c0 + 1][tt];
            s = fmaf(x0, x0, s); s = fmaf(x1, x1, s);
            __half h0 = __float2half_rn(x0), h1 = __float2half_rn(x1);
            hp[q] = (uint32_t)*(uint16_t*)&h0 | ((uint32_t)*(uint16_t*)&h1 << 16);
        }
        hbuf[tt][cc * 4 + c8] = make_uint4(hp[0], hp[1], hp[2], hp[3]);
    }
    psum[tt][cc] = s;
    __syncthreads();

    // coalesced write: each warp stores one full 512B token row per iteration
    {
        const int w = tid >> 5, lane = tid & 31;
        uint4* dst = (uint4*)g_Xh;
        #pragma unroll
        for (int t = 0; t < 4; t++) {
            int token = t * 8 + w;
            dst[(size_t)(b * HW + hw0 + token) * 32 + lane] = hbuf[token][lane];
        }
    }
    if (cc == 0) {
        float t = 0.f;
        #pragma unroll
        for (int q = 0; q < 8; q++) t += psum[tt][q];
        g_normX[b * HW + hw0 + tt] = t;
    }
}

// ---------------------------------------------------------------------------
// K2: fused hh HMMA GEMM over ALL code chunks, A tile resident in smem.
//   grid = 256 CTAs (one per 128 tokens). Candidate window vs running min.
// ---------------------------------------------------------------------------
__global__ void __launch_bounds__(256, 2) k_vq()
{
    extern __shared__ char smem[];    // [A: 64KB][B ring: 3 x 16KB]
    __shared__ uint32_t bestRow[TM];  // running min, float bits (all d > 0)
    __shared__ float nXs[TM];

    const int tid = threadIdx.x;
    const int tokenBase = blockIdx.x * TM;

    if (tid < TM) {
        bestRow[tid] = 0x7F800000u;   // +inf
        nXs[tid] = g_normX[tokenBase + tid];
    }

    const uint32_t sb = smem_u32(smem);
    const int ldr = tid >> 3, lds = tid & 7;

    // ---- prologue: stage resident A tile (4 ksub sub-tiles of 16KB)
    #pragma unroll
    for (int ksub = 0; ksub < 4; ksub++) {
        #pragma unroll
        for (int i = 0; i < 4; i++) {
            int r = ldr + i * 32;
            CP_ASYNC16(sb + ksub * B_STG + swaddr(r, lds),
                       g_Xh + (size_t)(tokenBase + r) * D + ksub * KCH + lds * 8);
        }
    }
    CP_COMMIT();

    auto issueB = [&](int s) {
        const int chunk = s >> 2, koff = (s & 3) * KCH;
        const uint32_t Bb = sb + A_BYTES + (s % NSTG) * B_STG;
        #pragma unroll
        for (int i = 0; i < 4; i++) {
            int r = ldr + i * 32;
            CP_ASYNC16(Bb + swaddr(r, lds),
                       g_Eh + (size_t)(chunk * TN + r) * D + koff + lds * 8);
        }
        CP_COMMIT();
    };

    issueB(0); issueB(1);

    const int lane = tid & 31, wid = tid >> 5;
    const int mrow0 = (wid & 1) * 64;
    const int ncol0 = (wid >> 1) * 32;
    const int lrow  = lane & 15, lhalf = lane >> 4;
    const float mE = g_maxE;

    float acc[4][4][4];
    #pragma unroll
    for (int m = 0; m < 4; m++)
        #pragma unroll
        for (int n = 0; n < 4; n++)
            #pragma unroll
            for (int q = 0; q < 4; q++) acc[m][n][q] = 0.f;

    for (int s = 0; s < NSTAGE; s++) {
        CP_WAIT1();
        __syncthreads();
        if (s + 2 < NSTAGE) issueB(s + 2);

        const uint32_t Ab = sb + (s & 3) * B_STG;            // resident A sub-tile
        const uint32_t Bb = sb + A_BYTES + (s % NSTG) * B_STG;

        #pragma unroll
        for (int k16 = 0; k16 < 4; k16++) {
            const int u = k16 * 2 + lhalf;
            uint32_t a[4][4], bfr[2][4];
            #pragma unroll
            for (int m = 0; m < 4; m++) {
                int r = mrow0 + m * 16 + lrow;
                LDSM_X4(a[m][0], a[m][1], a[m][2], a[m][3], Ab + swaddr(r, u));
            }
            #pragma unroll
            for (int nb = 0; nb < 2; nb++) {
                int r = ncol0 + nb * 16 + lrow;
                LDSM_X4(bfr[nb][0], bfr[nb][1], bfr[nb][2], bfr[nb][3], Bb + swaddr(r, u));
            }
            #pragma unroll
            for (int m = 0; m < 4; m++)
                #pragma unroll
                for (int n = 0; n < 4; n++)
                    MMA_F16(acc[m][n], a[m], bfr[n >> 1][n & 1], bfr[n >> 1][2 + (n & 1)]);
        }

        if ((s & 3) == 3) {
            // ---- chunk epilogue (no CTA barrier needed: superset-safe window)
            const int chunk = s >> 2;
            const int codeBase = chunk * TN;

            // pass 1: distances into acc + running row-min via 32-bit atomicMin
            #pragma unroll
            for (int m = 0; m < 4; m++) {
                #pragma unroll
                for (int rr = 0; rr < 2; rr++) {
                    const int row = mrow0 + m * 16 + (lane >> 2) + rr * 8;
                    const float nX = nXs[row];
                    float dmin = CUDART_INF_F;
                    #pragma unroll
                    for (int n = 0; n < 4; n++) {
                        #pragma unroll
                        for (int cc2 = 0; cc2 < 2; cc2++) {
                            float sdot = __fmul_rn(acc[m][n][rr * 2 + cc2], ESCL_INV);
                            float d = __fadd_rn(__fsub_rn(nX, __fmul_rn(2.0f, sdot)),
                                                g_normE[codeBase + ncol0 + n * 8 + 2 * (lane & 3) + cc2]);
                            acc[m][n][rr * 2 + cc2] = d;
                            dmin = fminf(dmin, d);
                        }
                    }
                    dmin = fminf(dmin, __shfl_xor_sync(0xFFFFFFFFu, dmin, 1));
                    dmin = fminf(dmin, __shfl_xor_sync(0xFFFFFFFFu, dmin, 2));
                    if ((lane & 3) == 0) atomicMin(&bestRow[row], __float_as_uint(dmin));
                }
            }
            // pass 2: collect candidates within 2T of running min (stale = superset)
            #pragma unroll
            for (int m = 0; m < 4; m++) {
                #pragma unroll
                for (int rr = 0; rr < 2; rr++) {
                    const int row = mrow0 + m * 16 + (lane >> 2) + rr * 8;
                    const float nX = nXs[row];
                    const float T = fmaf(T_COEF * sqrtf(nX), mE, T_SLACK);
                    const float thr = __uint_as_float(bestRow[row]) + 2.0f * T;
                    const int nglob = tokenBase + row;
                    #pragma unroll
                    for (int n = 0; n < 4; n++) {
                        #pragma unroll
                        for (int cc2 = 0; cc2 < 2; cc2++) {
                            float d = acc[m][n][rr * 2 + cc2];
                            if (d <= thr) {
                                const int col = ncol0 + n * 8 + 2 * (lane & 3) + cc2;
                                int slot = atomicAdd(&g_cnt[nglob], 1);
                                if (slot < CAND_CAP)
                                    g_cand[(size_t)nglob * CAND_CAP + slot] =
                                        ((unsigned long long)__float_as_uint(d) << 32) |
                                        (unsigned)(codeBase + col);
                            }
                            acc[m][n][rr * 2 + cc2] = 0.f;   // reset for next chunk
                        }
                    }
                }
            }
        }
    }
}

// ---------------------------------------------------------------------------
// K3: exact refine — warp per token; x row in registers (loaded on demand)
// ---------------------------------------------------------------------------
__global__ void k_refine(const float* __restrict__ E, const float* __restrict__ X)
{
    const int lane = threadIdx.x & 31;
    const int w    = threadIdx.x >> 5;
    const int n = blockIdx.x * 8 + w;
    const float nX = g_normX[n];
    const float T = fmaf(T_COEF * sqrtf(nX), g_maxE, T_SLACK);
    const int cnt = g_cnt[n];
    unsigned long long best = ~0ull;

    const int b  = n >> 10;
    const int hw = n & (HW - 1);
    const float* xsrc = X + (size_t)b * (D * HW) + hw;

    if (cnt <= CAND_CAP) {
        unsigned long long c = (lane < cnt) ? g_cand[(size_t)n * CAND_CAP + lane] : ~0ull;
        unsigned long long mn = c;
        #pragma unroll
        for (int o = 16; o > 0; o >>= 1) {
            unsigned long long t = __shfl_xor_sync(0xFFFFFFFFu, mn, o);
            mn = (t < mn) ? t : mn;
        }
        const float dmin = __uint_as_float((uint32_t)(mn >> 32));
        const float thr = dmin + 2.0f * T;
        const bool keep = (lane < cnt) &&
                          (__uint_as_float((uint32_t)(c >> 32)) <= thr);
        unsigned mask = __ballot_sync(0xFFFFFFFFu, keep);
        if (__popc(mask) == 1) {
            best = mn;                      // unique candidate: provably the argmin
        } else {
            float xr[8];
            #pragma unroll
            for (int j = 0; j < 8; j++)
                xr[j] = xsrc[(size_t)(lane * 8 + j) * HW];
            unsigned mm = mask;
            while (mm) {
                int bb = __ffs(mm) - 1; mm &= mm - 1;
                int kk = (int)__shfl_sync(0xFFFFFFFFu, (unsigned)(c & 0xFFFFFFFFu), bb);
                const float* er = E + (size_t)kk * D;
                float p = 0.f;
                #pragma unroll
                for (int j = 0; j < 8; j++)
                    p = fmaf(xr[j], er[lane * 8 + j], p);
                #pragma unroll
                for (int o = 16; o > 0; o >>= 1) p += __shfl_xor_sync(0xFFFFFFFFu, p, o);
                float d = __fadd_rn(__fsub_rn(nX, __fmul_rn(2.0f, p)), g_normE[kk]);
                unsigned long long key =
                    ((unsigned long long)__float_as_uint(d) << 32) | (unsigned)kk;
                best = (key < best) ? key : best;
            }
        }
    } else {
        // overflow fallback: exact cooperative full scan (essentially never taken)
        float xr[8];
        #pragma unroll
        for (int j = 0; j < 8; j++)
            xr[j] = xsrc[(size_t)(lane * 8 + j) * HW];
        for (int k0 = 0; k0 < K; k0++) {
            const float* er = E + (size_t)k0 * D;
            float p = 0.f;
            #pragma unroll
            for (int j = 0; j < 8; j++)
                p = fmaf(xr[j], er[lane * 8 + j], p);
            #pragma unroll
            for (int o = 16; o > 0; o >>= 1) p += __shfl_xor_sync(0xFFFFFFFFu, p, o);
            float d = __fadd_rn(__fsub_rn(nX, __fmul_rn(2.0f, p)), g_normE[k0]);
            unsigned long long key =
                ((unsigned long long)__float_as_uint(d) << 32) | (unsigned)k0;
            best = (key < best) ? key : best;
        }
    }
    if (lane == 0) g_idx[n] = (int)(best & 0xFFFFFFFFu);
}

// ---------------------------------------------------------------------------
// K4: gather (reference x+(q-x) rounding) + idx out + MSE partials
//   fp64 accumulation split into 4 independent chains (latency fix)
// ---------------------------------------------------------------------------
__global__ void k_gather(const float* __restrict__ X, const float* __restrict__ E,
                         float* __restrict__ Q, int writeQ,
                         float* __restrict__ outIdxF, int writeIdx)
{
    __shared__ double sred[256];
    const int tid = threadIdx.x;
    const int cb  = blockIdx.x >> 7;
    const int n   = (blockIdx.x & 127) * 256 + tid;
    const int b   = n >> 10;
    const int hw  = n & (HW - 1);
    const int ch0 = cb * 32;
    const float* xb = X + (size_t)b * (D * HW) + (size_t)ch0 * HW + hw;
    float*       qb = Q + (size_t)b * (D * HW) + (size_t)ch0 * HW + hw;
    const int idx = g_idx[n];
    const float* e = E + (size_t)idx * D + ch0;

    if (writeIdx && cb == 0) outIdxF[n] = (float)idx;

    double s0 = 0.0, s1 = 0.0, s2 = 0.0, s3 = 0.0;
    #pragma unroll
    for (int c4 = 0; c4 < 8; c4++) {
        float4 q4 = *(const float4*)(e + c4 * 4);
        float qv[4] = {q4.x, q4.y, q4.z, q4.w};
        float xv[4];
        #pragma unroll
        for (int j = 0; j < 4; j++) xv[j] = xb[(size_t)(c4 * 4 + j) * HW];
        #pragma unroll
        for (int j = 0; j < 4; j++) {
            float dd = __fsub_rn(qv[j], xv[j]);
            if (writeQ) qb[(size_t)(c4 * 4 + j) * HW] = __fadd_rn(xv[j], dd);
            double d64 = (double)dd;
            if (j == 0) s0 = fma(d64, d64, s0);
            else if (j == 1) s1 = fma(d64, d64, s1);
            else if (j == 2) s2 = fma(d64, d64, s2);
            else s3 = fma(d64, d64, s3);
        }
    }
    sred[tid] = (s0 + s1) + (s2 + s3);
    __syncthreads();
    for (int off = 128; off > 0; off >>= 1) {
        if (tid < off) sred[tid] += sred[tid + off];
        __syncthreads();
    }
    if (tid == 0) g_partial[blockIdx.x] = sred[0];
}

__global__ void k_loss(float* __restrict__ out, int lossOff)
{
    __shared__ double sd[256];
    int t = threadIdx.x;
    double s = 0.0;
    #pragma unroll
    for (int i = 0; i < 4; i++) s += g_partial[t * 4 + i];
    sd[t] = s;
    __syncthreads();
    for (int o = 128; o > 0; o >>= 1) {
        if (t < o) sd[t] += sd[t + o];
        __syncthreads();
    }
    if (t == 0) {
        float e = (float)(sd[0] / (double)((size_t)NTOK * D));
        out[lossOff] = e + 0.25f * e;
    }
}

// ---------------------------------------------------------------------------
extern "C" void kernel_launch(void* const* d_in, const int* in_sizes, int n_in,
                              void* d_out, int out_size)
{
    const float* X = (const float*)d_in[0];   // [32,256,32,32]
    const float* E = (const float*)d_in[1];   // [1024,256]
    float* out = (float*)d_out;

    const int qn = NTOK * D;
    int writeQ = 0, lossOff = -1, idxOff = -1;
    if (out_size >= qn) writeQ = 1;
    if (out_size == qn + 1 + NTOK) { lossOff = qn; idxOff = qn + 1; }
    else if (out_size == qn + 1)   { lossOff = qn; }
    else if (out_size == qn + NTOK){ idxOff = qn; }
    else if (out_size == NTOK)     { idxOff = 0; writeQ = 0; }

    cudaFuncSetAttribute(k_vq, cudaFuncAttributeMaxDynamicSharedMemorySize, SMEM_DYN);

    k_prep_e<<<8, 128>>>(E);
    k_split_x<<<NTOK / 32, 256>>>(X);
    k_vq<<<NTOK / TM, 256, SMEM_DYN>>>();
    k_refine<<<NTOK / 8, 256>>>(E, X);
    k_gather<<<1024, 256>>>(X, E, out, writeQ,
                            (idxOff >= 0) ? (out + idxOff) : out,
                            (idxOff >= 0) ? 1 : 0);
    if (lossOff >= 0)
        k_loss<<<1, 256>>>(out, lossOff);
}

// round 15
// speedup vs baseline: 1.1519x; 1.0069x over previous
#include <cuda_runtime.h>
#include <cuda_fp16.h>
#include <math_constants.h>
#include <cstdint>

// ---------------- problem constants ----------------
#define NTOK 32768      // 32*32*32 tokens
#define D    256        // embedding dim
#define K    1024       // codebook size
#define HW   1024       // H*W
#define TM   128        // tokens per CTA tile
#define TN   128        // codes per chunk
#define KCH  64         // dims per pipeline stage
#define NCHUNK 8        // K / TN
#define NSTAGE 32       // NCHUNK * (D/KCH)
#define NSTG 2          // cp.async B ring (2 => 96KB dyn => 2 CTAs/SM)
#define B_STG 16384     // 128 codes x 64 dims x 2B
#define A_BYTES 65536   // 128 tokens x 256 dims x 2B
#define SMEM_DYN (A_BYTES + NSTG * B_STG)   // 98304
#define CAND_CAP 32
#define ESCL      1024.0f          // 2^10 exact
#define ESCL_INV  9.765625e-4f     // 2^-10 exact
// |d_hh - d_exact| <= 4*2^-11*||x||*||e||max + slack
#define T_COEF  1.98e-3f
#define T_SLACK 2.0e-4f

// ---------------- device scratch (no allocations allowed) ----------------
__device__ __align__(256) __half g_Xh[NTOK * D];
__device__ __align__(256) __half g_Eh[K * D];      // fl16(e * 2^10)
__device__ float  g_normX[NTOK];
__device__ float  g_normE[K];
__device__ float  g_maxEblk[8];
__device__ float  g_maxE;
__device__ int    g_cnt[NTOK];
__device__ unsigned long long g_cand[NTOK * CAND_CAP];
__device__ int    g_idx[NTOK];
__device__ double g_partial[256];

__device__ __forceinline__ uint32_t smem_u32(const void* p) {
    uint32_t a;
    asm("{ .reg .u64 t; cvta.to.shared.u64 t, %1; cvt.u32.u64 %0, t; }" : "=r"(a) : "l"(p));
    return a;
}
#define CP_ASYNC16(saddr, gptr) \
    asm volatile("cp.async.cg.shared.global [%0], [%1], 16;" :: "r"(saddr), "l"(gptr))
#define CP_COMMIT() asm volatile("cp.async.commit_group;" ::: "memory")
#define CP_WAIT1()  asm volatile("cp.async.wait_group 1;" ::: "memory")
#define LDSM_X4(r0, r1, r2, r3, a) \
    asm volatile("ldmatrix.sync.aligned.m8n8.x4.shared.b16 {%0,%1,%2,%3}, [%4];" \
        : "=r"(r0), "=r"(r1), "=r"(r2), "=r"(r3) : "r"(a))
#define MMA_F16(d, a, b0v, b1v) \
    asm volatile("mma.sync.aligned.m16n8k16.row.col.f32.f16.f16.f32 " \
        "{%0,%1,%2,%3}, {%4,%5,%6,%7}, {%8,%9}, {%0,%1,%2,%3};" \
        : "+f"((d)[0]), "+f"((d)[1]), "+f"((d)[2]), "+f"((d)[3]) \
        : "r"((a)[0]), "r"((a)[1]), "r"((a)[2]), "r"((a)[3]), "r"(b0v), "r"(b1v))

__device__ __forceinline__ uint32_t swaddr(int row, int u) {
    return (uint32_t)(row * 128 + ((u ^ (row & 7)) << 4));
}

// ---------------------------------------------------------------------------
// K0: codebook fp16 (pre-scaled by 2^10) + squared norms + per-block max norm
// ---------------------------------------------------------------------------
__global__ void k_prep_e(const float* __restrict__ E) {
    __shared__ float red[128];
    int k = blockIdx.x * blockDim.x + threadIdx.x;
    const float* e = E + (size_t)k * D;
    float s = 0.f;
    #pragma unroll 8
    for (int c = 0; c < D; c++) {
        float x = e[c];
        s = fmaf(x, x, s);
        g_Eh[(size_t)k * D + c] = __float2half_rn(x * ESCL);  // normal-range fp16
    }
    g_normE[k] = s;
    red[threadIdx.x] = s;
    __syncthreads();
    for (int o = 64; o > 0; o >>= 1) {
        if (threadIdx.x < o) red[threadIdx.x] = fmaxf(red[threadIdx.x], red[threadIdx.x + o]);
        __syncthreads();
    }
    if (threadIdx.x == 0) g_maxEblk[blockIdx.x] = red[0];
}

// ---------------------------------------------------------------------------
// K1: transpose X -> token-major fp16 (coalesced via smem staging) + ||x||^2
// ---------------------------------------------------------------------------
__global__ void k_split_x(const float* __restrict__ X) {
    __shared__ float tile[D][33];
    __shared__ float psum[32][9];
    __shared__ uint4 hbuf[32][32];    // 32 tokens x 32 x 16B chunks (full rows)
    const int tid = threadIdx.x;
    const int b   = blockIdx.x >> 5;
    const int hw0 = (blockIdx.x & 31) * 32;
    const float* Xb = X + (size_t)b * (D * HW) + hw0;

    if (blockIdx.x == 0 && tid == 0) {       // finalize maxE (k_prep done: stream order)
        float m = 0.f;
        #pragma unroll
        for (int i = 0; i < 8; i++) m = fmaxf(m, g_maxEblk[i]);
        g_maxE = sqrtf(m);
    }
    if (tid < 32) g_cnt[b * HW + hw0 + tid] = 0;   // reset candidate counters

    {
        int w = tid >> 5, lane = tid & 31;
        #pragma unroll
        for (int c = w; c < D; c += 8) tile[c][lane] = Xb[(size_t)c * HW + lane];
    }
    __syncthreads();

    const int tt = tid >> 3;          // token 0..31
    const int cc = tid & 7;           // channel block (32 channels)
    float s = 0.f;
    #pragma unroll
    for (int c8 = 0; c8 < 4; c8++) {
        uint32_t hp[4];
        #pragma unroll
        for (int q = 0; q < 4; q++) {
            int c0 = cc * 32 + c8 * 8 + q * 2;
            float x0 = tile[c0][tt], x1 = tile[c0 + 1][tt];
            s = fmaf(x0, x0, s); s = fmaf(x1, x1, s);
            __half h0 = __float2half_rn(x0), h1 = __float2half_rn(x1);
            hp[q] = (uint32_t)*(uint16_t*)&h0 | ((uint32_t)*(uint16_t*)&h1 << 16);
        }
        hbuf[tt][cc * 4 + c8] = make_uint4(hp[0], hp[1], hp[2], hp[3]);
    }
    psum[tt][cc] = s;
    __syncthreads();

    // coalesced write: each warp stores one full 512B token row per iteration
    {
        const int w = tid >> 5, lane = tid & 31;
        uint4* dst = (uint4*)g_Xh;
        #pragma unroll
        for (int t = 0; t < 4; t++) {
            int token = t * 8 + w;
            dst[(size_t)(b * HW + hw0 + token) * 32 + lane] = hbuf[token][lane];
        }
    }
    if (cc == 0) {
        float t = 0.f;
        #pragma unroll
        for (int q = 0; q < 8; q++) t += psum[tt][q];
        g_normX[b * HW + hw0 + tt] = t;
    }
}

// ---------------------------------------------------------------------------
// K2: fused hh HMMA GEMM over ALL code chunks, A resident, 2-stage B ring.
//   96KB dynamic smem => 2 CTAs/SM => single wave of 256 CTAs.
// ---------------------------------------------------------------------------
__global__ void __launch_bounds__(256, 2) k_vq()
{
    extern __shared__ char smem[];    // [A: 64KB][B ring: 2 x 16KB]
    __shared__ uint32_t bestRow[TM];  // running min, float bits (all d > 0)
    __shared__ float nXs[TM];

    const int tid = threadIdx.x;
    const int tokenBase = blockIdx.x * TM;

    if (tid < TM) {
        bestRow[tid] = 0x7F800000u;   // +inf
        nXs[tid] = g_normX[tokenBase + tid];
    }

    const uint32_t sb = smem_u32(smem);
    const int ldr = tid >> 3, lds = tid & 7;

    // ---- prologue: stage resident A tile (4 ksub sub-tiles of 16KB)
    #pragma unroll
    for (int ksub = 0; ksub < 4; ksub++) {
        #pragma unroll
        for (int i = 0; i < 4; i++) {
            int r = ldr + i * 32;
            CP_ASYNC16(sb + ksub * B_STG + swaddr(r, lds),
                       g_Xh + (size_t)(tokenBase + r) * D + ksub * KCH + lds * 8);
        }
    }
    CP_COMMIT();

    auto issueB = [&](int s) {
        const int chunk = s >> 2, koff = (s & 3) * KCH;
        const uint32_t Bb = sb + A_BYTES + (s & (NSTG - 1)) * B_STG;
        #pragma unroll
        for (int i = 0; i < 4; i++) {
            int r = ldr + i * 32;
            CP_ASYNC16(Bb + swaddr(r, lds),
                       g_Eh + (size_t)(chunk * TN + r) * D + koff + lds * 8);
        }
        CP_COMMIT();
    };

    issueB(0); issueB(1);

    const int lane = tid & 31, wid = tid >> 5;
    const int mrow0 = (wid & 1) * 64;
    const int ncol0 = (wid >> 1) * 32;
    const int lrow  = lane & 15, lhalf = lane >> 4;
    const float mE = g_maxE;

    float acc[4][4][4];
    #pragma unroll
    for (int m = 0; m < 4; m++)
        #pragma unroll
        for (int n = 0; n < 4; n++)
            #pragma unroll
            for (int q = 0; q < 4; q++) acc[m][n][q] = 0.f;

    for (int s = 0; s < NSTAGE; s++) {
        CP_WAIT1();               // buffer s&1 complete (A also, on s=0)
        __syncthreads();

        const uint32_t Ab = sb + (s & 3) * B_STG;            // resident A sub-tile
        const uint32_t Bb = sb + A_BYTES + (s & (NSTG - 1)) * B_STG;

        #pragma unroll
        for (int k16 = 0; k16 < 4; k16++) {
            const int u = k16 * 2 + lhalf;
            uint32_t a[4][4], bfr[2][4];
            #pragma unroll
            for (int m = 0; m < 4; m++) {
                int r = mrow0 + m * 16 + lrow;
                LDSM_X4(a[m][0], a[m][1], a[m][2], a[m][3], Ab + swaddr(r, u));
            }
            #pragma unroll
            for (int nb = 0; nb < 2; nb++) {
                int r = ncol0 + nb * 16 + lrow;
                LDSM_X4(bfr[nb][0], bfr[nb][1], bfr[nb][2], bfr[nb][3], Bb + swaddr(r, u));
            }
            #pragma unroll
            for (int m = 0; m < 4; m++)
                #pragma unroll
                for (int n = 0; n < 4; n++)
                    MMA_F16(acc[m][n], a[m], bfr[n >> 1][n & 1], bfr[n >> 1][2 + (n & 1)]);
        }

        if ((s & 3) == 3) {
            // ---- chunk epilogue (superset-safe window vs running min)
            const int chunk = s >> 2;
            const int codeBase = chunk * TN;

            #pragma unroll
            for (int m = 0; m < 4; m++) {
                #pragma unroll
                for (int rr = 0; rr < 2; rr++) {
                    const int row = mrow0 + m * 16 + (lane >> 2) + rr * 8;
                    const float nX = nXs[row];
                    float dmin = CUDART_INF_F;
                    #pragma unroll
                    for (int n = 0; n < 4; n++) {
                        #pragma unroll
                        for (int cc2 = 0; cc2 < 2; cc2++) {
                            float sdot = __fmul_rn(acc[m][n][rr * 2 + cc2], ESCL_INV);
                            float d = __fadd_rn(__fsub_rn(nX, __fmul_rn(2.0f, sdot)),
                                                g_normE[codeBase + ncol0 + n * 8 + 2 * (lane & 3) + cc2]);
                            acc[m][n][rr * 2 + cc2] = d;
                            dmin = fminf(dmin, d);
                        }
                    }
                    dmin = fminf(dmin, __shfl_xor_sync(0xFFFFFFFFu, dmin, 1));
                    dmin = fminf(dmin, __shfl_xor_sync(0xFFFFFFFFu, dmin, 2));
                    if ((lane & 3) == 0) atomicMin(&bestRow[row], __float_as_uint(dmin));
                }
            }
            #pragma unroll
            for (int m = 0; m < 4; m++) {
                #pragma unroll
                for (int rr = 0; rr < 2; rr++) {
                    const int row = mrow0 + m * 16 + (lane >> 2) + rr * 8;
                    const float nX = nXs[row];
                    const float T = fmaf(T_COEF * sqrtf(nX), mE, T_SLACK);
                    const float thr = __uint_as_float(bestRow[row]) + 2.0f * T;
                    const int nglob = tokenBase + row;
                    #pragma unroll
                    for (int n = 0; n < 4; n++) {
                        #pragma unroll
                        for (int cc2 = 0; cc2 < 2; cc2++) {
                            float d = acc[m][n][rr * 2 + cc2];
                            if (d <= thr) {
                                const int col = ncol0 + n * 8 + 2 * (lane & 3) + cc2;
                                int slot = atomicAdd(&g_cnt[nglob], 1);
                                if (slot < CAND_CAP)
                                    g_cand[(size_t)nglob * CAND_CAP + slot] =
                                        ((unsigned long long)__float_as_uint(d) << 32) |
                                        (unsigned)(codeBase + col);
                            }
                            acc[m][n][rr * 2 + cc2] = 0.f;   // reset for next chunk
                        }
                    }
                }
            }
        }

        __syncthreads();                       // all reads of buf s&1 done
        if (s + 2 < NSTAGE) issueB(s + 2);     // safe to overwrite buf s&1
    }
}

// ---------------------------------------------------------------------------
// K3: exact refine — warp per token; x row in registers (loaded on demand)
// ---------------------------------------------------------------------------
__global__ void k_refine(const float* __restrict__ E, const float* __restrict__ X)
{
    const int lane = threadIdx.x & 31;
    const int w    = threadIdx.x >> 5;
    const int n = blockIdx.x * 8 + w;
    const float nX = g_normX[n];
    const float T = fmaf(T_COEF * sqrtf(nX), g_maxE, T_SLACK);
    const int cnt = g_cnt[n];
    unsigned long long best = ~0ull;

    const int b  = n >> 10;
    const int hw = n & (HW - 1);
    const float* xsrc = X + (size_t)b * (D * HW) + hw;

    if (cnt <= CAND_CAP) {
        unsigned long long c = (lane < cnt) ? g_cand[(size_t)n * CAND_CAP + lane] : ~0ull;
        unsigned long long mn = c;
        #pragma unroll
        for (int o = 16; o > 0; o >>= 1) {
            unsigned long long t = __shfl_xor_sync(0xFFFFFFFFu, mn, o);
            mn = (t < mn) ? t : mn;
        }
        const float dmin = __uint_as_float((uint32_t)(mn >> 32));
        const float thr = dmin + 2.0f * T;
        const bool keep = (lane < cnt) &&
                          (__uint_as_float((uint32_t)(c >> 32)) <= thr);
        unsigned mask = __ballot_sync(0xFFFFFFFFu, keep);
        if (__popc(mask) == 1) {
            best = mn;                      // unique candidate: provably the argmin
        } else {
            float xr[8];
            #pragma unroll
            for (int j = 0; j < 8; j++)
                xr[j] = xsrc[(size_t)(lane * 8 + j) * HW];
            unsigned mm = mask;
            while (mm) {
                int bb = __ffs(mm) - 1; mm &= mm - 1;
                int kk = (int)__shfl_sync(0xFFFFFFFFu, (unsigned)(c & 0xFFFFFFFFu), bb);
                const float* er = E + (size_t)kk * D;
                float p = 0.f;
                #pragma unroll
                for (int j = 0; j < 8; j++)
                    p = fmaf(xr[j], er[lane * 8 + j], p);
                #pragma unroll
                for (int o = 16; o > 0; o >>= 1) p += __shfl_xor_sync(0xFFFFFFFFu, p, o);
                float d = __fadd_rn(__fsub_rn(nX, __fmul_rn(2.0f, p)), g_normE[kk]);
                unsigned long long key =
                    ((unsigned long long)__float_as_uint(d) << 32) | (unsigned)kk;
                best = (key < best) ? key : best;
            }
        }
    } else {
        // overflow fallback: exact cooperative full scan (essentially never taken)
        float xr[8];
        #pragma unroll
        for (int j = 0; j < 8; j++)
            xr[j] = xsrc[(size_t)(lane * 8 + j) * HW];
        for (int k0 = 0; k0 < K; k0++) {
            const float* er = E + (size_t)k0 * D;
            float p = 0.f;
            #pragma unroll
            for (int j = 0; j < 8; j++)
                p = fmaf(xr[j], er[lane * 8 + j], p);
            #pragma unroll
            for (int o = 16; o > 0; o >>= 1) p += __shfl_xor_sync(0xFFFFFFFFu, p, o);
            float d = __fadd_rn(__fsub_rn(nX, __fmul_rn(2.0f, p)), g_normE[k0]);
            unsigned long long key =
                ((unsigned long long)__float_as_uint(d) << 32) | (unsigned)k0;
            best = (key < best) ? key : best;
        }
    }
    if (lane == 0) g_idx[n] = (int)(best & 0xFFFFFFFFu);
}

// ---------------------------------------------------------------------------
// K4: gather — 4 tokens/thread, float4 X/Q traffic, ref x+(q-x) rounding
//   grid: 8 channel-chunks x 32 token-blocks (1024 tokens per block)
// ---------------------------------------------------------------------------
__global__ void k_gather(const float* __restrict__ X, const float* __restrict__ E,
                         float* __restrict__ Q, int writeQ,
                         float* __restrict__ outIdxF, int writeIdx)
{
    __shared__ double sred[256];
    const int tid = threadIdx.x;
    const int cb  = blockIdx.x >> 5;            // channel chunk 0..7
    const int n0  = (blockIdx.x & 31) * 1024 + tid * 4;   // 4 consecutive tokens
    const int b   = n0 >> 10;
    const int hw  = n0 & (HW - 1);
    const int ch0 = cb * 32;
    const float* xb = X + (size_t)b * (D * HW) + (size_t)ch0 * HW + hw;
    float*       qb = Q + (size_t)b * (D * HW) + (size_t)ch0 * HW + hw;

    int idx[4];
    #pragma unroll
    for (int t = 0; t < 4; t++) idx[t] = g_idx[n0 + t];
    if (writeIdx && cb == 0) {
        #pragma unroll
        for (int t = 0; t < 4; t++) outIdxF[n0 + t] = (float)idx[t];
    }
    const float* e0 = E + (size_t)idx[0] * D + ch0;
    const float* e1 = E + (size_t)idx[1] * D + ch0;
    const float* e2 = E + (size_t)idx[2] * D + ch0;
    const float* e3 = E + (size_t)idx[3] * D + ch0;

    double s0 = 0.0, s1 = 0.0, s2 = 0.0, s3 = 0.0;
    #pragma unroll
    for (int c4 = 0; c4 < 8; c4++) {
        float4 ef[4];
        ef[0] = *(const float4*)(e0 + c4 * 4);
        ef[1] = *(const float4*)(e1 + c4 * 4);
        ef[2] = *(const float4*)(e2 + c4 * 4);
        ef[3] = *(const float4*)(e3 + c4 * 4);
        #pragma unroll
        for (int j = 0; j < 4; j++) {
            const int c = c4 * 4 + j;
            float4 x4 = *(const float4*)(xb + (size_t)c * HW);
            float d0 = __fsub_rn(((const float*)&ef[0])[j], x4.x);
            float d1 = __fsub_rn(((const float*)&ef[1])[j], x4.y);
            float d2 = __fsub_rn(((const float*)&ef[2])[j], x4.z);
            float d3 = __fsub_rn(((const float*)&ef[3])[j], x4.w);
            if (writeQ) {
                float4 q4 = make_float4(__fadd_rn(x4.x, d0), __fadd_rn(x4.y, d1),
                                        __fadd_rn(x4.z, d2), __fadd_rn(x4.w, d3));
                *(float4*)(qb + (size_t)c * HW) = q4;
            }
            s0 = fma((double)d0, (double)d0, s0);
            s1 = fma((double)d1, (double)d1, s1);
            s2 = fma((double)d2, (double)d2, s2);
            s3 = fma((double)d3, (double)d3, s3);
        }
    }
    sred[tid] = (s0 + s1) + (s2 + s3);
    __syncthreads();
    for (int off = 128; off > 0; off >>= 1) {
        if (tid < off) sred[tid] += sred[tid + off];
        __syncthreads();
    }
    if (tid == 0) g_partial[blockIdx.x] = sred[0];
}

__global__ void k_loss(float* __restrict__ out, int lossOff)
{
    __shared__ double sd[256];
    int t = threadIdx.x;
    sd[t] = g_partial[t];
    __syncthreads();
    for (int o = 128; o > 0; o >>= 1) {
        if (t < o) sd[t] += sd[t + o];
        __syncthreads();
    }
    if (t == 0) {
        float e = (float)(sd[0] / (double)((size_t)NTOK * D));
        out[lossOff] = e + 0.25f * e;
    }
}

// ---------------------------------------------------------------------------
extern "C" void kernel_launch(void* const* d_in, const int* in_sizes, int n_in,
                              void* d_out, int out_size)
{
    const float* X = (const float*)d_in[0];   // [32,256,32,32]
    const float* E = (const float*)d_in[1];   // [1024,256]
    float* out = (float*)d_out;

    const int qn = NTOK * D;
    int writeQ = 0, lossOff = -1, idxOff = -1;
    if (out_size >= qn) writeQ = 1;
    if (out_size == qn + 1 + NTOK) { lossOff = qn; idxOff = qn + 1; }
    else if (out_size == qn + 1)   { lossOff = qn; }
    else if (out_size == qn + NTOK){ idxOff = qn; }
    else if (out_size == NTOK)     { idxOff = 0; writeQ = 0; }

    cudaFuncSetAttribute(k_vq, cudaFuncAttributeMaxDynamicSharedMemorySize, SMEM_DYN);

    k_prep_e<<<8, 128>>>(E);
    k_split_x<<<NTOK / 32, 256>>>(X);
    k_vq<<<NTOK / TM, 256, SMEM_DYN>>>();
    k_refine<<<NTOK / 8, 256>>>(E, X);
    k_gather<<<256, 256>>>(X, E, out, writeQ,
                           (idxOff >= 0) ? (out + idxOff) : out,
                           (idxOff >= 0) ? 1 : 0);
    if (lossOff >= 0)
        k_loss<<<1, 256>>>(out, lossOff);
}